// round 12
// baseline (speedup 1.0000x reference)
#include <cuda_runtime.h>
#include <cuda_fp16.h>
#include <cstdint>
#include <cstddef>

#define L_SEQ  2048
#define NHID_C 512
#define DMODEL 1024
#define BATCH  8

// Scratch (allocation-free)
__device__ __half g_qkvh [(size_t)BATCH * 3 * DMODEL * L_SEQ];   // [b][3072][2048]
__device__ __half g_att2h[(size_t)BATCH * L_SEQ * DMODEL];       // [b][2048][1024] transposed
__device__ __half g_xth  [(size_t)BATCH * L_SEQ * NHID_C];       // [b][2048][512]
__device__ __half g_wth  [3 * DMODEL * NHID_C];                  // [3072][512] m-major,k-contig
__device__ __half g_woth [NHID_C * DMODEL];                      // [512][1024]
__device__ float  g_bcat [3 * DMODEL];

// ---------------------------------------------------------------------------
// helpers
// ---------------------------------------------------------------------------
__device__ __forceinline__ void ldsm_x4(uint32_t* r, uint32_t addr) {
    asm volatile("ldmatrix.sync.aligned.m8n8.x4.shared.b16 {%0,%1,%2,%3}, [%4];"
        : "=r"(r[0]), "=r"(r[1]), "=r"(r[2]), "=r"(r[3]) : "r"(addr));
}
__device__ __forceinline__ void mma_f16(float* c, const uint32_t* a, uint32_t b0, uint32_t b1) {
    asm volatile("mma.sync.aligned.m16n8k16.row.col.f32.f16.f16.f32 "
        "{%0,%1,%2,%3}, {%4,%5,%6,%7}, {%8,%9}, {%0,%1,%2,%3};"
        : "+f"(c[0]), "+f"(c[1]), "+f"(c[2]), "+f"(c[3])
        : "r"(a[0]), "r"(a[1]), "r"(a[2]), "r"(a[3]), "r"(b0), "r"(b1));
}

// ---------------------------------------------------------------------------
// Fused prepass: one launch. Regions by blockIdx.x:
//  [0, 8192)            x transpose  (b, c-tile, l-tile)
//  [8192, 9728)         wq|wk|wv transpose (512x1024 -> [1024][512] each)
//  [9728, 10240)        wo transpose (1024x512 -> [512][1024])
//  [10240]              bias concat
// ---------------------------------------------------------------------------
__global__ void __launch_bounds__(256) prep_kernel(
    const float* __restrict__ x,
    const float* __restrict__ wq, const float* __restrict__ wk,
    const float* __restrict__ wv, const float* __restrict__ wo,
    const float* __restrict__ bq, const float* __restrict__ bk,
    const float* __restrict__ bv,
    __half* __restrict__ xt, __half* __restrict__ wth,
    __half* __restrict__ woth, float* __restrict__ bcat)
{
    __shared__ float tile[32][33];
    const int bid = blockIdx.x;
    const int tx = threadIdx.x & 31, ty = threadIdx.x >> 5;   // 32x8

    if (bid < 8192) {
        int b = bid >> 10, r = bid & 1023;
        int c0 = (r >> 6) << 5, l0 = (r & 63) << 5;
        const float* src = x + (size_t)b * NHID_C * L_SEQ;
        #pragma unroll
        for (int i = 0; i < 32; i += 8)
            tile[ty + i][tx] = src[(size_t)(c0 + ty + i) * L_SEQ + l0 + tx];
        __syncthreads();
        __half* dst = xt + (size_t)b * L_SEQ * NHID_C;
        #pragma unroll
        for (int i = 0; i < 32; i += 8)
            dst[(size_t)(l0 + ty + i) * NHID_C + c0 + tx] = __float2half_rn(tile[tx][ty + i]);
    } else if (bid < 8192 + 1536) {
        int q = bid - 8192;
        int mat = q >> 9, tl = q & 511;
        int c0 = (tl >> 4) << 5;    // src col tile (C=1024)
        int r0 = (tl & 15) << 5;    // src row tile (R=512)
        const float* src = (mat == 0) ? wq : (mat == 1) ? wk : wv;
        #pragma unroll
        for (int i = 0; i < 32; i += 8)
            tile[ty + i][tx] = src[(size_t)(r0 + ty + i) * 1024 + c0 + tx];
        __syncthreads();
        __half* dst = wth + (size_t)mat * 1024 * 512;
        #pragma unroll
        for (int i = 0; i < 32; i += 8)
            dst[(size_t)(c0 + ty + i) * 512 + r0 + tx] = __float2half_rn(tile[tx][ty + i]);
    } else if (bid < 8192 + 1536 + 512) {
        int q = bid - 8192 - 1536;
        int c0 = (q & 15) << 5;     // src col tile (C=512)
        int r0 = (q >> 4) << 5;     // src row tile (R=1024)
        #pragma unroll
        for (int i = 0; i < 32; i += 8)
            tile[ty + i][tx] = wo[(size_t)(r0 + ty + i) * 512 + c0 + tx];
        __syncthreads();
        #pragma unroll
        for (int i = 0; i < 32; i += 8)
            woth[(size_t)(c0 + ty + i) * 1024 + r0 + tx] = __float2half_rn(tile[tx][ty + i]);
    } else {
        int t = threadIdx.x;
        for (int i = t; i < 1024; i += 256) {
            bcat[i]        = bq[i];
            bcat[1024 + i] = bk[i];
            bcat[2048 + i] = bv[i];
        }
    }
}

// ---------------------------------------------------------------------------
// fp16 GEMM: O[b, m, n] = sum_k A[m, k] * X[b, n, k] + bias[m]
// CTA 128m x 128n, k-tile 64, 4 warps (warp 64x64), mma m16n8k16,
// ldmatrix + SW128 swizzle, 3-stage cp.async, 2 CTAs/SM.
// ---------------------------------------------------------------------------
#define GSTAGES     3
#define TILE_BYTES  16384
#define STAGE_BYTES 32768
#define GEMM_SMEM   (GSTAGES * STAGE_BYTES + 1024)

__global__ void __launch_bounds__(128, 2) gemm_f16_kernel(
    const __half* __restrict__ A,
    const __half* __restrict__ X,
    const float* __restrict__ bias,
    void* __restrict__ Optr,
    int Kdim, int Mtot, int outHalf)
{
    extern __shared__ char smem_raw[];
    const uint32_t sbase =
        ((uint32_t)__cvta_generic_to_shared(smem_raw) + 1023u) & ~1023u;

    const int b  = blockIdx.z;
    const int m0 = blockIdx.y * 128;
    const int n0 = blockIdx.x * 128;
    const int tid  = threadIdx.x;
    const int warp = tid >> 5, lane = tid & 31;
    const int wm = (warp >> 1) * 64;
    const int wn = (warp & 1) * 64;

    const __half* Xb = X + (size_t)b * 2048 * Kdim;

    float acc[4][8][4];
    #pragma unroll
    for (int i = 0; i < 4; i++)
        #pragma unroll
        for (int j = 0; j < 8; j++)
            #pragma unroll
            for (int r = 0; r < 4; r++) acc[i][j][r] = 0.f;

    const int rowa = wm + (lane & 15);
    const int ktopA = ((lane >> 4) & 1) * 16;
    uint32_t aOff[4], aXor[4];
    #pragma unroll
    for (int i = 0; i < 4; i++) {
        int r = rowa + i * 16;
        aOff[i] = (uint32_t)(r * 128);
        aXor[i] = (uint32_t)((r & 7) << 4);
    }
    const int rowb = wn + (lane & 7) + ((lane >> 4) & 1) * 8;
    const int kofsB = ((lane >> 3) & 1) * 16;
    uint32_t bOff[4], bXor[4];
    #pragma unroll
    for (int jp = 0; jp < 4; jp++) {
        int r = rowb + jp * 16;
        bOff[jp] = (uint32_t)(r * 128);
        bXor[jp] = (uint32_t)((r & 7) << 4);
    }

    const int T = Kdim >> 6;

    auto issue = [&](int t, int s) {
        const int kt = t << 6;
        uint32_t aB = sbase + (uint32_t)(s * STAGE_BYTES);
        uint32_t bB = aB + TILE_BYTES;
        #pragma unroll
        for (int p = 0; p < 8; p++) {
            int idx = p * 128 + tid;
            int row = idx >> 3, c = idx & 7;
            uint32_t so = (uint32_t)(row * 128) + (uint32_t)((c * 16) ^ ((row & 7) << 4));
            const __half* sA = A + (size_t)(m0 + row) * Kdim + kt + c * 8;
            asm volatile("cp.async.cg.shared.global [%0], [%1], 16;\n"
                         :: "r"(aB + so), "l"(sA));
            const __half* sB = Xb + (size_t)(n0 + row) * Kdim + kt + c * 8;
            asm volatile("cp.async.cg.shared.global [%0], [%1], 16;\n"
                         :: "r"(bB + so), "l"(sB));
        }
    };

    #pragma unroll
    for (int t = 0; t < GSTAGES - 1; t++) {
        if (t < T) issue(t, t);
        asm volatile("cp.async.commit_group;\n");
    }

    int stage = 0;
    for (int t = 0; t < T; t++) {
        asm volatile("cp.async.wait_group %0;\n" :: "n"(GSTAGES - 2));
        __syncthreads();

        int pf = t + GSTAGES - 1;
        if (pf < T) issue(pf, pf % GSTAGES);
        asm volatile("cp.async.commit_group;\n");

        uint32_t stA = sbase + (uint32_t)(stage * STAGE_BYTES);
        uint32_t stB = stA + TILE_BYTES;
        stage = (stage + 1 == GSTAGES) ? 0 : stage + 1;

        #pragma unroll
        for (int kk2 = 0; kk2 < 128; kk2 += 32) {
            uint32_t a[4][4];
            #pragma unroll
            for (int i = 0; i < 4; i++)
                ldsm_x4(a[i], stA + aOff[i] + (((uint32_t)(kk2 + ktopA)) ^ aXor[i]));
            uint32_t bb[4][4];
            #pragma unroll
            for (int jp = 0; jp < 4; jp++)
                ldsm_x4(bb[jp], stB + bOff[jp] + (((uint32_t)(kk2 + kofsB)) ^ bXor[jp]));
            #pragma unroll
            for (int i = 0; i < 4; i++)
                #pragma unroll
                for (int j = 0; j < 8; j++)
                    mma_f16(acc[i][j], a[i], bb[j >> 1][(j & 1) * 2], bb[j >> 1][(j & 1) * 2 + 1]);
        }
    }

    const int g  = lane >> 2;
    const int tq = lane & 3;
    __half* Oh = (__half*)Optr + (size_t)b * Mtot * 2048;
    float*  Of = (float*)Optr + (size_t)b * Mtot * 2048;
    #pragma unroll
    for (int i = 0; i < 4; i++) {
        int r0 = m0 + wm + i * 16 + g;
        float bv0 = bias[r0];
        float bv1 = bias[r0 + 8];
        #pragma unroll
        for (int j = 0; j < 8; j++) {
            int col = n0 + wn + j * 8 + tq * 2;
            float v0 = acc[i][j][0] + bv0, v1 = acc[i][j][1] + bv0;
            float v2 = acc[i][j][2] + bv1, v3 = acc[i][j][3] + bv1;
            if (outHalf) {
                *(__half2*)(Oh + (size_t)r0 * 2048 + col)       = __floats2half2_rn(v0, v1);
                *(__half2*)(Oh + (size_t)(r0 + 8) * 2048 + col) = __floats2half2_rn(v2, v3);
            } else {
                *(float2*)(Of + (size_t)r0 * 2048 + col)       = make_float2(v0, v1);
                *(float2*)(Of + (size_t)(r0 + 8) * 2048 + col) = make_float2(v2, v3);
            }
        }
    }
}

// ---------------------------------------------------------------------------
// Attention: block = (b, h, 512 l), 128 threads, 4 l per thread.
// Tap: f=3c'+w -> channel f&1023, l-shift (f>>10)-1 (warp-uniform per (d,w)).
// Writes transposed att2t[b][l2][c2]: l2=(l&31)*64+d, c2=h*64+(l>>5).
// ---------------------------------------------------------------------------
#define ATT_PAD  514
#define ATT_SMEM (64 * ATT_PAD * 2)    // 65792 B

__global__ void __launch_bounds__(128) attn_kernel(__half* __restrict__ att2t)
{
    extern __shared__ __half att_sm[];
    const int b = blockIdx.z, h = blockIdx.y;
    const int l0 = blockIdx.x * 512;
    const int t = threadIdx.x;
    const int l = l0 + 4 * t;
    const int lw0 = l >> 1;

    const __half2* base2 = (const __half2*)(g_qkvh + (size_t)b * 3 * DMODEL * L_SEQ);
    const __half2* Q2 = base2;
    const __half2* K2 = base2 + (size_t)DMODEL * 1024;
    const __half2* V2 = base2 + (size_t)2 * DMODEL * 1024;
    const int c0 = h * 64;

    float lg[3][4] = {{0.f,0.f,0.f,0.f},{0.f,0.f,0.f,0.f},{0.f,0.f,0.f,0.f}};
    #pragma unroll 4
    for (int d = 0; d < 64; d++) {
        int cp = c0 + d;
        const __half2* Qr = Q2 + (size_t)cp * 1024;
        float2 qa = __half22float2(Qr[lw0]);
        float2 qb = __half22float2(Qr[lw0 + 1]);
        int f = 3 * cp;
        #pragma unroll
        for (int w = 0; w < 3; w++) {
            int ff = f + w, cc = ff & 1023, dl = (ff >> 10) - 1;
            const __half2* R = K2 + (size_t)cc * 1024;
            float2 m0 = __half22float2(R[lw0]);
            float2 m1 = __half22float2(R[lw0 + 1]);
            if (dl == 0) {
                lg[w][0] += qa.x * m0.x; lg[w][1] += qa.y * m0.y;
                lg[w][2] += qb.x * m1.x; lg[w][3] += qb.y * m1.y;
            } else if (dl < 0) {
                float e = (l > 0) ? __high2float(R[lw0 - 1]) : 0.f;
                lg[w][0] += qa.x * e;    lg[w][1] += qa.y * m0.x;
                lg[w][2] += qb.x * m0.y; lg[w][3] += qb.y * m1.x;
            } else {
                float e = (l + 4 < 2048) ? __low2float(R[lw0 + 2]) : 0.f;
                lg[w][0] += qa.x * m0.y; lg[w][1] += qa.y * m1.x;
                lg[w][2] += qb.x * m1.y; lg[w][3] += qb.y * e;
            }
        }
    }

    float aw[3][4];
    #pragma unroll
    for (int li = 0; li < 4; li++) {
        float m  = fmaxf(lg[0][li], fmaxf(lg[1][li], lg[2][li]));
        float e0 = __expf((lg[0][li] - m) * 0.125f);
        float e1 = __expf((lg[1][li] - m) * 0.125f);
        float e2 = __expf((lg[2][li] - m) * 0.125f);
        float inv = 1.f / (e0 + e1 + e2);
        aw[0][li] = e0 * inv; aw[1][li] = e1 * inv; aw[2][li] = e2 * inv;
    }

    #pragma unroll 4
    for (int d = 0; d < 64; d++) {
        int cp = c0 + d;
        int f = 3 * cp;
        float s0 = 0.f, s1 = 0.f, s2 = 0.f, s3 = 0.f;
        #pragma unroll
        for (int w = 0; w < 3; w++) {
            int ff = f + w, cc = ff & 1023, dl = (ff >> 10) - 1;
            const __half2* R = V2 + (size_t)cc * 1024;
            float2 m0 = __half22float2(R[lw0]);
            float2 m1 = __half22float2(R[lw0 + 1]);
            if (dl == 0) {
                s0 += aw[w][0] * m0.x; s1 += aw[w][1] * m0.y;
                s2 += aw[w][2] * m1.x; s3 += aw[w][3] * m1.y;
            } else if (dl < 0) {
                float e = (l > 0) ? __high2float(R[lw0 - 1]) : 0.f;
                s0 += aw[w][0] * e;    s1 += aw[w][1] * m0.x;
                s2 += aw[w][2] * m0.y; s3 += aw[w][3] * m1.x;
            } else {
                float e = (l + 4 < 2048) ? __low2float(R[lw0 + 2]) : 0.f;
                s0 += aw[w][0] * m0.y; s1 += aw[w][1] * m1.x;
                s2 += aw[w][2] * m1.y; s3 += aw[w][3] * e;
            }
        }
        *(__half2*)&att_sm[d * ATT_PAD + 4 * t]     = __floats2half2_rn(s0, s1);
        *(__half2*)&att_sm[d * ATT_PAD + 4 * t + 2] = __floats2half2_rn(s2, s3);
    }
    __syncthreads();

    // gather + transposed store: 2048 rows (lsub 0..31 x d 0..63), 16 halves each
    const int c2base = h * 64 + (l0 >> 5);
    __half* outb = att2t + (size_t)b * L_SEQ * DMODEL;
    #pragma unroll
    for (int it = 0; it < 16; it++) {
        int r = it * 128 + t;
        int d = r & 63, lsub = r >> 6;
        unsigned ow[8];
        #pragma unroll
        for (int i = 0; i < 8; i++) {
            __half v0 = att_sm[d * ATT_PAD + (2 * i) * 32 + lsub];
            __half v1 = att_sm[d * ATT_PAD + (2 * i + 1) * 32 + lsub];
            __half2 p = __halves2half2(v0, v1);
            ow[i] = *(unsigned*)&p;
        }
        __half* pdst = outb + (size_t)(lsub * 64 + d) * DMODEL + c2base;
        *(uint4*)pdst       = make_uint4(ow[0], ow[1], ow[2], ow[3]);
        *((uint4*)pdst + 1) = make_uint4(ow[4], ow[5], ow[6], ow[7]);
    }
}

// ---------------------------------------------------------------------------
extern "C" void kernel_launch(void* const* d_in, const int* in_sizes, int n_in,
                              void* d_out, int out_size)
{
    const float* x  = (const float*)d_in[0];
    const float* wq = (const float*)d_in[1];
    const float* bq = (const float*)d_in[2];
    const float* wk = (const float*)d_in[3];
    const float* bk = (const float*)d_in[4];
    const float* wv = (const float*)d_in[5];
    const float* bv = (const float*)d_in[6];
    const float* wo = (const float*)d_in[7];
    const float* bo = (const float*)d_in[8];
    float* out = (float*)d_out;

    __half* qkvh;  cudaGetSymbolAddress((void**)&qkvh,  g_qkvh);
    __half* att2h; cudaGetSymbolAddress((void**)&att2h, g_att2h);
    __half* xth;   cudaGetSymbolAddress((void**)&xth,   g_xth);
    __half* wth;   cudaGetSymbolAddress((void**)&wth,   g_wth);
    __half* woth;  cudaGetSymbolAddress((void**)&woth,  g_woth);
    float*  bcat;  cudaGetSymbolAddress((void**)&bcat,  g_bcat);

    // 1) fused prepass (one launch)
    prep_kernel<<<8192 + 1536 + 512 + 1, 256>>>(
        x, wq, wk, wv, wo, bq, bk, bv, xth, wth, woth, bcat);

    cudaFuncSetAttribute(gemm_f16_kernel,
                         cudaFuncAttributeMaxDynamicSharedMemorySize, GEMM_SMEM);
    cudaFuncSetAttribute(attn_kernel,
                         cudaFuncAttributeMaxDynamicSharedMemorySize, ATT_SMEM);

    // 2) GEMM1: qkv = wt * xt. M=3072, K=512, N=2048 per batch. half out.
    gemm_f16_kernel<<<dim3(16, 24, BATCH), 128, GEMM_SMEM>>>(
        wth, xth, bcat, qkvh, NHID_C, 3 * DMODEL, 1);

    // 3) Attention: 4 l-tiles x 16 heads x 8 batches, 128 threads.
    attn_kernel<<<dim3(4, 16, BATCH), 128, ATT_SMEM>>>(att2h);

    // 4) GEMM2: out = wot * att2t. M=512, K=1024, N=2048 per batch. float out.
    gemm_f16_kernel<<<dim3(16, 4, BATCH), 128, GEMM_SMEM>>>(
        woth, att2h, bo, out, DMODEL, NHID_C, 0);
}

// round 17
// speedup vs baseline: 2.2411x; 2.2411x over previous
#include <cuda_runtime.h>
#include <cuda_fp16.h>
#include <cstdint>
#include <cstddef>

#define L_SEQ  2048
#define NHID_C 512
#define DMODEL 1024
#define BATCH  8

// Scratch (allocation-free)
__device__ __half g_qkvh [(size_t)BATCH * 3 * DMODEL * L_SEQ];   // [b][3072][2048]
__device__ __half g_att2h[(size_t)BATCH * L_SEQ * DMODEL];       // [b][2048][1024] transposed
__device__ __half g_xth  [(size_t)BATCH * L_SEQ * NHID_C];       // [b][2048][512]
__device__ __half g_wth  [3 * DMODEL * NHID_C];                  // [3072][512] m-major,k-contig
__device__ __half g_woth [NHID_C * DMODEL];                      // [512][1024]
__device__ float  g_bcat [3 * DMODEL];

// ---------------------------------------------------------------------------
// helpers
// ---------------------------------------------------------------------------
__device__ __forceinline__ void ldsm_x4(uint32_t* r, uint32_t addr) {
    asm volatile("ldmatrix.sync.aligned.m8n8.x4.shared.b16 {%0,%1,%2,%3}, [%4];"
        : "=r"(r[0]), "=r"(r[1]), "=r"(r[2]), "=r"(r[3]) : "r"(addr));
}
__device__ __forceinline__ void mma_f16(float* c, const uint32_t* a, uint32_t b0, uint32_t b1) {
    asm volatile("mma.sync.aligned.m16n8k16.row.col.f32.f16.f16.f32 "
        "{%0,%1,%2,%3}, {%4,%5,%6,%7}, {%8,%9}, {%0,%1,%2,%3};"
        : "+f"(c[0]), "+f"(c[1]), "+f"(c[2]), "+f"(c[3])
        : "r"(a[0]), "r"(a[1]), "r"(a[2]), "r"(a[3]), "r"(b0), "r"(b1));
}

// ---------------------------------------------------------------------------
// Fused prepass (one launch). Regions by blockIdx.x:
//  [0, 8192)      x transpose
//  [8192, 9728)   wq|wk|wv transpose
//  [9728, 10240)  wo transpose
//  [10240]        bias concat
// ---------------------------------------------------------------------------
__global__ void __launch_bounds__(256) prep_kernel(
    const float* __restrict__ x,
    const float* __restrict__ wq, const float* __restrict__ wk,
    const float* __restrict__ wv, const float* __restrict__ wo,
    const float* __restrict__ bq, const float* __restrict__ bk,
    const float* __restrict__ bv,
    __half* __restrict__ xt, __half* __restrict__ wth,
    __half* __restrict__ woth, float* __restrict__ bcat)
{
    __shared__ float tile[32][33];
    const int bid = blockIdx.x;
    const int tx = threadIdx.x & 31, ty = threadIdx.x >> 5;

    if (bid < 8192) {
        int b = bid >> 10, r = bid & 1023;
        int c0 = (r >> 6) << 5, l0 = (r & 63) << 5;
        const float* src = x + (size_t)b * NHID_C * L_SEQ;
        #pragma unroll
        for (int i = 0; i < 32; i += 8)
            tile[ty + i][tx] = src[(size_t)(c0 + ty + i) * L_SEQ + l0 + tx];
        __syncthreads();
        __half* dst = xt + (size_t)b * L_SEQ * NHID_C;
        #pragma unroll
        for (int i = 0; i < 32; i += 8)
            dst[(size_t)(l0 + ty + i) * NHID_C + c0 + tx] = __float2half_rn(tile[tx][ty + i]);
    } else if (bid < 8192 + 1536) {
        int q = bid - 8192;
        int mat = q >> 9, tl = q & 511;
        int c0 = (tl >> 4) << 5;
        int r0 = (tl & 15) << 5;
        const float* src = (mat == 0) ? wq : (mat == 1) ? wk : wv;
        #pragma unroll
        for (int i = 0; i < 32; i += 8)
            tile[ty + i][tx] = src[(size_t)(r0 + ty + i) * 1024 + c0 + tx];
        __syncthreads();
        __half* dst = wth + (size_t)mat * 1024 * 512;
        #pragma unroll
        for (int i = 0; i < 32; i += 8)
            dst[(size_t)(c0 + ty + i) * 512 + r0 + tx] = __float2half_rn(tile[tx][ty + i]);
    } else if (bid < 8192 + 1536 + 512) {
        int q = bid - 8192 - 1536;
        int c0 = (q & 15) << 5;
        int r0 = (q >> 4) << 5;
        #pragma unroll
        for (int i = 0; i < 32; i += 8)
            tile[ty + i][tx] = wo[(size_t)(r0 + ty + i) * 512 + c0 + tx];
        __syncthreads();
        #pragma unroll
        for (int i = 0; i < 32; i += 8)
            woth[(size_t)(c0 + ty + i) * 1024 + r0 + tx] = __float2half_rn(tile[tx][ty + i]);
    } else {
        int t = threadIdx.x;
        for (int i = t; i < 1024; i += 256) {
            bcat[i]        = bq[i];
            bcat[1024 + i] = bk[i];
            bcat[2048 + i] = bv[i];
        }
    }
}

// ---------------------------------------------------------------------------
// fp16 GEMM: O[b, m, n] = sum_k A[m, k] * X[b, n, k] + bias[m]
// CTA 128m x 128n, k-tile 64, 4 warps (warp 64x64), mma m16n8k16,
// ldmatrix + SW128 swizzle, 3-stage cp.async, 2 CTAs/SM.  (R11-proven)
// ---------------------------------------------------------------------------
#define GSTAGES     3
#define TILE_BYTES  16384
#define STAGE_BYTES 32768
#define GEMM_SMEM   (GSTAGES * STAGE_BYTES + 1024)

__global__ void __launch_bounds__(128, 2) gemm_f16_kernel(
    const __half* __restrict__ A,
    const __half* __restrict__ X,
    const float* __restrict__ bias,
    void* __restrict__ Optr,
    int Kdim, int Mtot, int outHalf)
{
    extern __shared__ char smem_raw[];
    const uint32_t sbase =
        ((uint32_t)__cvta_generic_to_shared(smem_raw) + 1023u) & ~1023u;

    const int b  = blockIdx.z;
    const int m0 = blockIdx.y * 128;
    const int n0 = blockIdx.x * 128;
    const int tid  = threadIdx.x;
    const int warp = tid >> 5, lane = tid & 31;
    const int wm = (warp >> 1) * 64;
    const int wn = (warp & 1) * 64;

    const __half* Xb = X + (size_t)b * 2048 * Kdim;

    float acc[4][8][4];
    #pragma unroll
    for (int i = 0; i < 4; i++)
        #pragma unroll
        for (int j = 0; j < 8; j++)
            #pragma unroll
            for (int r = 0; r < 4; r++) acc[i][j][r] = 0.f;

    const int rowa = wm + (lane & 15);
    const int ktopA = ((lane >> 4) & 1) * 16;
    uint32_t aOff[4], aXor[4];
    #pragma unroll
    for (int i = 0; i < 4; i++) {
        int r = rowa + i * 16;
        aOff[i] = (uint32_t)(r * 128);
        aXor[i] = (uint32_t)((r & 7) << 4);
    }
    const int rowb = wn + (lane & 7) + ((lane >> 4) & 1) * 8;
    const int kofsB = ((lane >> 3) & 1) * 16;
    uint32_t bOff[4], bXor[4];
    #pragma unroll
    for (int jp = 0; jp < 4; jp++) {
        int r = rowb + jp * 16;
        bOff[jp] = (uint32_t)(r * 128);
        bXor[jp] = (uint32_t)((r & 7) << 4);
    }

    const int T = Kdim >> 6;

    auto issue = [&](int t, int s) {
        const int kt = t << 6;
        uint32_t aB = sbase + (uint32_t)(s * STAGE_BYTES);
        uint32_t bB = aB + TILE_BYTES;
        #pragma unroll
        for (int p = 0; p < 8; p++) {
            int idx = p * 128 + tid;
            int row = idx >> 3, c = idx & 7;
            uint32_t so = (uint32_t)(row * 128) + (uint32_t)((c * 16) ^ ((row & 7) << 4));
            const __half* sA = A + (size_t)(m0 + row) * Kdim + kt + c * 8;
            asm volatile("cp.async.cg.shared.global [%0], [%1], 16;\n"
                         :: "r"(aB + so), "l"(sA));
            const __half* sB = Xb + (size_t)(n0 + row) * Kdim + kt + c * 8;
            asm volatile("cp.async.cg.shared.global [%0], [%1], 16;\n"
                         :: "r"(bB + so), "l"(sB));
        }
    };

    #pragma unroll
    for (int t = 0; t < GSTAGES - 1; t++) {
        if (t < T) issue(t, t);
        asm volatile("cp.async.commit_group;\n");
    }

    int stage = 0;
    for (int t = 0; t < T; t++) {
        asm volatile("cp.async.wait_group %0;\n" :: "n"(GSTAGES - 2));
        __syncthreads();

        int pf = t + GSTAGES - 1;
        if (pf < T) issue(pf, pf % GSTAGES);
        asm volatile("cp.async.commit_group;\n");

        uint32_t stA = sbase + (uint32_t)(stage * STAGE_BYTES);
        uint32_t stB = stA + TILE_BYTES;
        stage = (stage + 1 == GSTAGES) ? 0 : stage + 1;

        #pragma unroll
        for (int kk2 = 0; kk2 < 128; kk2 += 32) {
            uint32_t a[4][4];
            #pragma unroll
            for (int i = 0; i < 4; i++)
                ldsm_x4(a[i], stA + aOff[i] + (((uint32_t)(kk2 + ktopA)) ^ aXor[i]));
            uint32_t bb[4][4];
            #pragma unroll
            for (int jp = 0; jp < 4; jp++)
                ldsm_x4(bb[jp], stB + bOff[jp] + (((uint32_t)(kk2 + kofsB)) ^ bXor[jp]));
            #pragma unroll
            for (int i = 0; i < 4; i++)
                #pragma unroll
                for (int j = 0; j < 8; j++)
                    mma_f16(acc[i][j], a[i], bb[j >> 1][(j & 1) * 2], bb[j >> 1][(j & 1) * 2 + 1]);
        }
    }

    const int g  = lane >> 2;
    const int tq = lane & 3;
    __half* Oh = (__half*)Optr + (size_t)b * Mtot * 2048;
    float*  Of = (float*)Optr + (size_t)b * Mtot * 2048;
    #pragma unroll
    for (int i = 0; i < 4; i++) {
        int r0 = m0 + wm + i * 16 + g;
        float bv0 = bias[r0];
        float bv1 = bias[r0 + 8];
        #pragma unroll
        for (int j = 0; j < 8; j++) {
            int col = n0 + wn + j * 8 + tq * 2;
            float v0 = acc[i][j][0] + bv0, v1 = acc[i][j][1] + bv0;
            float v2 = acc[i][j][2] + bv1, v3 = acc[i][j][3] + bv1;
            if (outHalf) {
                *(__half2*)(Oh + (size_t)r0 * 2048 + col)       = __floats2half2_rn(v0, v1);
                *(__half2*)(Oh + (size_t)(r0 + 8) * 2048 + col) = __floats2half2_rn(v2, v3);
            } else {
                *(float2*)(Of + (size_t)r0 * 2048 + col)       = make_float2(v0, v1);
                *(float2*)(Of + (size_t)(r0 + 8) * 2048 + col) = make_float2(v2, v3);
            }
        }
    }
}

// ---------------------------------------------------------------------------
// Attention: R10-proven thread-per-l structure, fp16 I/O.
// Block = (b, h, 512 l), 256 threads x 2 strided l-passes.
// Per (d, tap): ONE predicated coalesced 2B load. fp32 accumulation.
// Output: transposed att2t[b][l2][c2], l2=(l&31)*64+d, c2=h*64+(l>>5);
// block covers 16 consecutive c2 -> full 32B-sector rows.
// ---------------------------------------------------------------------------
#define ATT_PAD  514                    // halves per smem row (odd word stride)
#define ATT_SMEM (64 * ATT_PAD * 2)     // 65792 B

__global__ void __launch_bounds__(256) attn_kernel(__half* __restrict__ att2t)
{
    extern __shared__ __half att_sm[];  // [64][ATT_PAD]
    const int b = blockIdx.z, h = blockIdx.y;
    const int l0 = blockIdx.x * 512;
    const int t = threadIdx.x;
    const __half* base = g_qkvh + (size_t)b * 3 * DMODEL * L_SEQ;
    const __half* Q = base;
    const __half* K = base + (size_t)DMODEL * L_SEQ;
    const __half* V = base + (size_t)2 * DMODEL * L_SEQ;
    const int c0 = h * 64;

    #pragma unroll
    for (int hf = 0; hf < 2; hf++) {
        const int lloc = hf * 256 + t;
        const int l = l0 + lloc;

        float lg0 = 0.f, lg1 = 0.f, lg2 = 0.f;
        #pragma unroll 8
        for (int d = 0; d < 64; d++) {
            int cp = c0 + d;
            float qv = __half2float(Q[(size_t)cp * L_SEQ + l]);
            int f = 3 * cp;
            #pragma unroll
            for (int w = 0; w < 3; w++) {
                int ff = f + w;
                int cc = ff & 1023;
                int ll = l + (ff >> 10) - 1;
                float kv = (ll >= 0 && ll < L_SEQ)
                         ? __half2float(K[(size_t)cc * L_SEQ + ll]) : 0.f;
                if (w == 0) lg0 += qv * kv;
                else if (w == 1) lg1 += qv * kv;
                else lg2 += qv * kv;
            }
        }
        float m  = fmaxf(lg0, fmaxf(lg1, lg2));
        float e0 = __expf((lg0 - m) * 0.125f);
        float e1 = __expf((lg1 - m) * 0.125f);
        float e2 = __expf((lg2 - m) * 0.125f);
        float inv = 1.f / (e0 + e1 + e2);
        float a0 = e0 * inv, a1 = e1 * inv, a2 = e2 * inv;

        #pragma unroll 8
        for (int d = 0; d < 64; d++) {
            int cp = c0 + d;
            int f = 3 * cp;
            float s = 0.f;
            #pragma unroll
            for (int w = 0; w < 3; w++) {
                int ff = f + w;
                int cc = ff & 1023;
                int ll = l + (ff >> 10) - 1;
                float vv = (ll >= 0 && ll < L_SEQ)
                         ? __half2float(V[(size_t)cc * L_SEQ + ll]) : 0.f;
                s += (w == 0 ? a0 : (w == 1 ? a1 : a2)) * vv;
            }
            att_sm[d * ATT_PAD + lloc] = __float2half_rn(s);
        }
    }
    __syncthreads();

    // gather + transposed store: 2048 rows (lsub 0..31, d 0..63), 32B each
    const int c2base = h * 64 + (l0 >> 5);
    __half* outb = att2t + (size_t)b * L_SEQ * DMODEL;
    #pragma unroll
    for (int it = 0; it < 8; it++) {
        int r = it * 256 + t;
        int d = r & 63, lsub = r >> 6;
        unsigned ow[8];
        #pragma unroll
        for (int i = 0; i < 8; i++) {
            __half v0 = att_sm[d * ATT_PAD + (2 * i) * 32 + lsub];
            __half v1 = att_sm[d * ATT_PAD + (2 * i + 1) * 32 + lsub];
            __half2 p = __halves2half2(v0, v1);
            ow[i] = *(unsigned*)&p;
        }
        __half* pdst = outb + (size_t)(lsub * 64 + d) * DMODEL + c2base;
        *(uint4*)pdst       = make_uint4(ow[0], ow[1], ow[2], ow[3]);
        *((uint4*)pdst + 1) = make_uint4(ow[4], ow[5], ow[6], ow[7]);
    }
}

// ---------------------------------------------------------------------------
extern "C" void kernel_launch(void* const* d_in, const int* in_sizes, int n_in,
                              void* d_out, int out_size)
{
    const float* x  = (const float*)d_in[0];
    const float* wq = (const float*)d_in[1];
    const float* bq = (const float*)d_in[2];
    const float* wk = (const float*)d_in[3];
    const float* bk = (const float*)d_in[4];
    const float* wv = (const float*)d_in[5];
    const float* bv = (const float*)d_in[6];
    const float* wo = (const float*)d_in[7];
    const float* bo = (const float*)d_in[8];
    float* out = (float*)d_out;

    __half* qkvh;  cudaGetSymbolAddress((void**)&qkvh,  g_qkvh);
    __half* att2h; cudaGetSymbolAddress((void**)&att2h, g_att2h);
    __half* xth;   cudaGetSymbolAddress((void**)&xth,   g_xth);
    __half* wth;   cudaGetSymbolAddress((void**)&wth,   g_wth);
    __half* woth;  cudaGetSymbolAddress((void**)&woth,  g_woth);
    float*  bcat;  cudaGetSymbolAddress((void**)&bcat,  g_bcat);

    // 1) fused prepass
    prep_kernel<<<8192 + 1536 + 512 + 1, 256>>>(
        x, wq, wk, wv, wo, bq, bk, bv, xth, wth, woth, bcat);

    cudaFuncSetAttribute(gemm_f16_kernel,
                         cudaFuncAttributeMaxDynamicSharedMemorySize, GEMM_SMEM);
    cudaFuncSetAttribute(attn_kernel,
                         cudaFuncAttributeMaxDynamicSharedMemorySize, ATT_SMEM);

    // 2) GEMM1: qkv = wt * xt. M=3072, K=512, N=2048 per batch. half out.
    gemm_f16_kernel<<<dim3(16, 24, BATCH), 128, GEMM_SMEM>>>(
        wth, xth, bcat, qkvh, NHID_C, 3 * DMODEL, 1);

    // 3) Attention: 4 l-tiles x 16 heads x 8 batches.
    attn_kernel<<<dim3(4, 16, BATCH), 256, ATT_SMEM>>>(att2h);

    // 4) GEMM2: out = wot * att2t. M=512, K=1024, N=2048 per batch. float out.
    gemm_f16_kernel<<<dim3(16, 4, BATCH), 128, GEMM_SMEM>>>(
        woth, att2h, bo, out, DMODEL, NHID_C, 0);
}